// round 12
// baseline (speedup 1.0000x reference)
#include <cuda_runtime.h>
#include <cuda_fp16.h>
#include <cstdint>
#include <math.h>

// ----------------------------------------------------------------------------
// DiT block: adaLN -> self-attn -> cross-attn -> MLP (GELU tanh)
// Round 12: 128-row attention tiles (8 warps), templated BM GEMM,
//           batched transposes.
// ----------------------------------------------------------------------------

#define Bx 4
#define Nx 1024
#define Dx 1024
#define Hx 16
#define HDx 64
#define TDx 768
#define TLx 77
#define ROWS (Bx * Nx)       // 4096
#define CTXROWS (Bx * TLx)   // 308

// fp32 scratch
__device__ float g_mod[Bx * 6 * Dx];
__device__ float g_x1[ROWS * Dx];
__device__ float g_x2[ROWS * Dx];
// half scratch
__device__ __half g_h[ROWS * Dx];
__device__ __half g_qkv[ROWS * 3 * Dx];
__device__ __half g_attn_h[ROWS * Dx];
__device__ __half g_q2[ROWS * Dx];
__device__ __half g_k2v2[CTXROWS * 2 * Dx];
__device__ __half g_ctx_h[CTXROWS * Dx];
__device__ __half g_text_h[CTXROWS * TDx];
__device__ __half g_hid_h[ROWS * 4 * Dx];
// transposed (K-major [N,K]) fp16 weights
__device__ __half g_Wqkv_t[3 * Dx * Dx];
__device__ __half g_Wproj_t[Dx * Dx];
__device__ __half g_Wctx_t[Dx * TDx];
__device__ __half g_Wq_t[Dx * Dx];
__device__ __half g_Wkv_t[2 * Dx * Dx];
__device__ __half g_Wout_t[Dx * Dx];
__device__ __half g_Wfc1_t[4 * Dx * Dx];
__device__ __half g_Wfc2_t[4 * Dx * Dx];

// ----------------------------------------------------------------------------
// helpers
// ----------------------------------------------------------------------------
__device__ __forceinline__ uint32_t smem_u32(const void* p) {
    uint32_t a;
    asm("{ .reg .u64 t; cvta.to.shared.u64 t, %1; cvt.u32.u64 %0, t; }"
        : "=r"(a) : "l"(p));
    return a;
}
__device__ __forceinline__ void cp_async16(uint32_t saddr, const void* gaddr, int szbytes) {
    asm volatile("cp.async.cg.shared.global [%0], [%1], 16, %2;"
                 :: "r"(saddr), "l"(gaddr), "r"(szbytes) : "memory");
}
#define CP_COMMIT() asm volatile("cp.async.commit_group;" ::: "memory")
#define CP_WAIT(n)  asm volatile("cp.async.wait_group %0;" :: "n"(n) : "memory")

#define LDMATRIX_X4(r0, r1, r2, r3, addr) \
    asm volatile("ldmatrix.sync.aligned.m8n8.x4.shared.b16 {%0,%1,%2,%3}, [%4];" \
                 : "=r"(r0), "=r"(r1), "=r"(r2), "=r"(r3) : "r"(addr))
#define LDMATRIX_X4_T(r0, r1, r2, r3, addr) \
    asm volatile("ldmatrix.sync.aligned.m8n8.x4.trans.shared.b16 {%0,%1,%2,%3}, [%4];" \
                 : "=r"(r0), "=r"(r1), "=r"(r2), "=r"(r3) : "r"(addr))

__device__ __forceinline__ void mma_f16(float& c0, float& c1, float& c2, float& c3,
                                        uint32_t a0, uint32_t a1, uint32_t a2, uint32_t a3,
                                        uint32_t b0, uint32_t b1) {
    asm volatile(
        "mma.sync.aligned.m16n8k16.row.col.f32.f16.f16.f32 "
        "{%0,%1,%2,%3}, {%4,%5,%6,%7}, {%8,%9}, {%0,%1,%2,%3};"
        : "+f"(c0), "+f"(c1), "+f"(c2), "+f"(c3)
        : "r"(a0), "r"(a1), "r"(a2), "r"(a3), "r"(b0), "r"(b1));
}
__device__ __forceinline__ uint32_t pack_h2(float lo, float hi) {
    __half2 h = __floats2half2_rn(lo, hi);
    return *(uint32_t*)&h;
}

// ----------------------------------------------------------------------------
// batched weight transpose
// ----------------------------------------------------------------------------
#define NTJOBS 9
struct TransJobs {
    const float* in[NTJOBS];
    __half* out[NTJOBS];
    int K[NTJOBS];
    int N[NTJOBS];
    int base[NTJOBS];
};

__global__ void transpose_batch_kernel(TransJobs jobs) {
    __shared__ float t[32][33];
    int bid = blockIdx.x;
    int j = 0;
    #pragma unroll
    for (int i = 1; i < NTJOBS; i++)
        if (bid >= jobs.base[i]) j = i;
    int tloc = bid - jobs.base[j];
    int K = jobs.K[j], N = jobs.N[j];
    int tiles_x = N >> 5;
    int n0 = (tloc % tiles_x) << 5;
    int k0 = (tloc / tiles_x) << 5;
    const float* in = jobs.in[j];
    __half* out = jobs.out[j];
    int tx = threadIdx.x, ty = threadIdx.y;
    #pragma unroll
    for (int i = 0; i < 32; i += 8)
        t[ty + i][tx] = in[(size_t)(k0 + ty + i) * N + n0 + tx];
    __syncthreads();
    #pragma unroll
    for (int i = 0; i < 32; i += 8)
        out[(size_t)(n0 + ty + i) * K + k0 + tx] = __float2half(t[tx][ty + i]);
}

__global__ void f2h_kernel(const float* __restrict__ in, __half* __restrict__ out, int n) {
    int i = blockIdx.x * 256 + threadIdx.x;
    if (i < n) out[i] = __float2half(in[i]);
}

// ----------------------------------------------------------------------------
// adaLN modulation
// ----------------------------------------------------------------------------
__global__ void ada_mod_kernel(const float* __restrict__ c,
                               const float* __restrict__ Wada,
                               const float* __restrict__ bada,
                               float* __restrict__ mod) {
    __shared__ float sc[Dx];
    int b = blockIdx.y;
    for (int i = threadIdx.x; i < Dx; i += 256) {
        float v = c[b * Dx + i];
        sc[i] = v / (1.f + __expf(-v));
    }
    __syncthreads();
    int n = blockIdx.x * 256 + threadIdx.x;
    float acc = 0.f;
    for (int k = 0; k < Dx; k++)
        acc += sc[k] * Wada[(size_t)k * (6 * Dx) + n];
    mod[b * 6 * Dx + n] = acc + bada[n];
}

// ----------------------------------------------------------------------------
// LayerNorm + modulate -> fp16
// ----------------------------------------------------------------------------
__global__ void ln_mod_kernel(const float* __restrict__ x,
                              const float* __restrict__ mod,
                              __half* __restrict__ out, int chunk) {
    int row = blockIdx.x;
    int b = row >> 10;
    int tid = threadIdx.x;
    const float* xr = x + (size_t)row * Dx;
    float4 v = *(const float4*)(xr + tid * 4);
    float s = v.x + v.y + v.z + v.w;
    float ss = v.x * v.x + v.y * v.y + v.z * v.z + v.w * v.w;
    #pragma unroll
    for (int off = 16; off; off >>= 1) {
        s  += __shfl_xor_sync(0xffffffffu, s, off);
        ss += __shfl_xor_sync(0xffffffffu, ss, off);
    }
    __shared__ float rs[8], rss[8];
    int wid = tid >> 5, lane = tid & 31;
    if (!lane) { rs[wid] = s; rss[wid] = ss; }
    __syncthreads();
    s = 0.f; ss = 0.f;
    #pragma unroll
    for (int w = 0; w < 8; w++) { s += rs[w]; ss += rss[w]; }
    float mean = s * (1.f / Dx);
    float var = ss * (1.f / Dx) - mean * mean;
    float inv = rsqrtf(var + 1e-6f);
    const float* sh = mod + (size_t)b * 6 * Dx + (size_t)chunk * Dx;
    const float* scl = sh + Dx;
    int d = tid * 4;
    float o0 = (v.x - mean) * inv * (1.f + scl[d + 0]) + sh[d + 0];
    float o1 = (v.y - mean) * inv * (1.f + scl[d + 1]) + sh[d + 1];
    float o2 = (v.z - mean) * inv * (1.f + scl[d + 2]) + sh[d + 2];
    float o3 = (v.w - mean) * inv * (1.f + scl[d + 3]) + sh[d + 3];
    __half2* op = (__half2*)(out + (size_t)row * Dx + d);
    op[0] = __floats2half2_rn(o0, o1);
    op[1] = __floats2half2_rn(o2, o3);
}

// ----------------------------------------------------------------------------
// fp16 mma.sync GEMM, cp.async 3-stage, templated M-tile (BM = 128 or 64)
// (unchanged from round 11 — proven)
// ----------------------------------------------------------------------------
#define ACT_NONE 0
#define ACT_GELU 1
#define STAGES 3

__device__ __forceinline__ float gelu_tanh(float x) {
    float x3 = x * x * x;
    return 0.5f * x * (1.f + tanhf(0.7978845608028654f * (x + 0.044715f * x3)));
}

template <int BM>
__global__ __launch_bounds__(256, 2)
void h_mma_gemm(const __half* __restrict__ A, const __half* __restrict__ BT,
                const float* __restrict__ bias, const float* __restrict__ res,
                float* __restrict__ Cf, __half* __restrict__ Ch,
                int M, int N, int K, int act) {
    constexpr int STAGE_BYTES = (BM + 128) * 128;
    constexpr int ACH = BM / 32;
    constexpr int IM = BM / 32;
    extern __shared__ char smem[];
    uint32_t sbase = smem_u32(smem);
    int tid = threadIdx.x, lane = tid & 31, wid = tid >> 5;
    int wm = wid >> 2, wn = wid & 3;
    int row0 = blockIdx.y * BM, col0 = blockIdx.x * 128;

    uint32_t offA[4], offB[4];
    const __half* gA[4];
    const __half* gB[4];
    int szA[4];
    #pragma unroll
    for (int i = 0; i < ACH; i++) {
        int idx = tid + i * 256;
        int r = idx >> 3, c8 = idx & 7;
        offA[i] = (uint32_t)(r * 128 + ((c8 ^ (r & 7)) << 4));
        szA[i] = (row0 + r) < M ? 16 : 0;
        gA[i] = A + (size_t)(row0 + r) * K + c8 * 8;
    }
    #pragma unroll
    for (int i = 0; i < 4; i++) {
        int idx = tid + i * 256;
        int r = idx >> 3, c8 = idx & 7;
        offB[i] = (uint32_t)(BM * 128 + r * 128 + ((c8 ^ (r & 7)) << 4));
        gB[i] = BT + (size_t)(col0 + r) * K + c8 * 8;
    }

    float acc[IM][4][4];
    #pragma unroll
    for (int im = 0; im < IM; im++)
        #pragma unroll
        for (int jn = 0; jn < 4; jn++)
            #pragma unroll
            for (int e = 0; e < 4; e++) acc[im][jn][e] = 0.f;

    int K64 = K >> 6;

    #pragma unroll
    for (int s = 0; s < STAGES - 1; s++) {
        uint32_t sa = sbase + (uint32_t)(s * STAGE_BYTES);
        #pragma unroll
        for (int i = 0; i < ACH; i++)
            cp_async16(sa + offA[i], gA[i] + (size_t)s * 64, szA[i]);
        #pragma unroll
        for (int i = 0; i < 4; i++)
            cp_async16(sa + offB[i], gB[i] + (size_t)s * 64, 16);
        CP_COMMIT();
    }

    int lrA = (lane & 7) | (lane & 8);
    int lkA8 = (lane >> 4) << 3;
    int lrB = (lane & 7) | ((lane & 16) >> 1);
    int lkB8 = lane & 8;

    for (int s = 0; s < K64; s++) {
        CP_WAIT(STAGES - 2);
        __syncthreads();
        uint32_t sa = sbase + (uint32_t)((s % STAGES) * STAGE_BYTES);
        uint32_t sb = sa + (uint32_t)(BM * 128);

        #pragma unroll
        for (int kg = 0; kg < 4; kg++) {
            int lkA = kg * 16 + lkA8;
            int lkB = kg * 16 + lkB8;
            uint32_t areg[IM][4];
            #pragma unroll
            for (int im = 0; im < IM; im++) {
                int r = wm * (BM / 2) + im * 16 + lrA;
                uint32_t addr = sa + (uint32_t)(r * 128 + (((lkA >> 3) ^ (r & 7)) << 4));
                LDMATRIX_X4(areg[im][0], areg[im][1], areg[im][2], areg[im][3], addr);
            }
            uint32_t breg[2][4];
            #pragma unroll
            for (int p = 0; p < 2; p++) {
                int r = wn * 32 + p * 16 + lrB;
                uint32_t addr = sb + (uint32_t)(r * 128 + (((lkB >> 3) ^ (r & 7)) << 4));
                LDMATRIX_X4(breg[p][0], breg[p][1], breg[p][2], breg[p][3], addr);
            }
            #pragma unroll
            for (int im = 0; im < IM; im++)
                #pragma unroll
                for (int jn = 0; jn < 4; jn++) {
                    int p = jn >> 1, q = (jn & 1) * 2;
                    mma_f16(acc[im][jn][0], acc[im][jn][1],
                            acc[im][jn][2], acc[im][jn][3],
                            areg[im][0], areg[im][1], areg[im][2], areg[im][3],
                            breg[p][q], breg[p][q + 1]);
                }
        }

        int sn = s + STAGES - 1;
        if (sn < K64) {
            uint32_t sa2 = sbase + (uint32_t)((sn % STAGES) * STAGE_BYTES);
            #pragma unroll
            for (int i = 0; i < ACH; i++)
                cp_async16(sa2 + offA[i], gA[i] + (size_t)sn * 64, szA[i]);
            #pragma unroll
            for (int i = 0; i < 4; i++)
                cp_async16(sa2 + offB[i], gB[i] + (size_t)sn * 64, 16);
        }
        CP_COMMIT();
    }

    int egr = lane >> 2, egc = (lane & 3) * 2;
    #pragma unroll
    for (int im = 0; im < IM; im++) {
        #pragma unroll
        for (int half = 0; half < 2; half++) {
            int rg = row0 + wm * (BM / 2) + im * 16 + egr + half * 8;
            if (rg >= M) continue;
            #pragma unroll
            for (int jn = 0; jn < 4; jn++) {
                int cg = col0 + wn * 32 + jn * 8 + egc;
                float t0 = acc[im][jn][half * 2 + 0];
                float t1 = acc[im][jn][half * 2 + 1];
                if (bias) { t0 += bias[cg]; t1 += bias[cg + 1]; }
                if (act == ACT_GELU) { t0 = gelu_tanh(t0); t1 = gelu_tanh(t1); }
                if (res) {
                    t0 += res[(size_t)rg * N + cg];
                    t1 += res[(size_t)rg * N + cg + 1];
                }
                if (Ch) {
                    *(__half2*)(Ch + (size_t)rg * N + cg) = __floats2half2_rn(t0, t1);
                } else {
                    *(float2*)(Cf + (size_t)rg * N + cg) = make_float2(t0, t1);
                }
            }
        }
    }
}

#define GEMM_SMEM_128 (STAGES * (128 + 128) * 128)
#define GEMM_SMEM_64  (STAGES * (64 + 128) * 128)

// ----------------------------------------------------------------------------
// fp16 ldmatrix/mma flash attention, 128 q-rows per CTA (8 warps),
// double-buffered K/V. smem: sQ 16KB | stage0 16KB | stage1 16KB = 48KB.
// ----------------------------------------------------------------------------
#define ATTN_SMEM (16384 + 2 * 16384)

__global__ __launch_bounds__(256, 2)
void attn_h_kernel(const __half* __restrict__ Q, int qStride,
                   const __half* __restrict__ K, const __half* __restrict__ V,
                   int kStride, __half* __restrict__ O, int Lq, int Lk) {
    extern __shared__ char smc[];
    uint32_t sQ = smem_u32(smc);

    int tid = threadIdx.x, lane = tid & 31, w = tid >> 5;   // 8 warps
    int gr = lane >> 2, lc = lane & 3;
    int qt = blockIdx.x, h = blockIdx.y, b = blockIdx.z;
    int wr = w * 16;
    const float scale = 0.125f;

    const __half* Kbase = K + (size_t)(b * Lk) * kStride + h * 64;
    const __half* Vbase = V + (size_t)(b * Lk) * kStride + h * 64;
    int nkt = (Lk + 63) >> 6;

    // prologue: Q tile (128 rows) + K/V tile 0, one commit group
    const __half* Qbase = Q + (size_t)(b * Lq + qt * 128) * qStride + h * 64;
    #pragma unroll
    for (int i = 0; i < 4; i++) {
        int idx = tid + i * 256;            // 0..1023
        int r = idx >> 3, c8 = idx & 7;
        cp_async16(sQ + r * 128 + ((c8 ^ (r & 7)) << 4),
                   Qbase + (size_t)r * qStride + c8 * 8, 16);
    }
    {
        uint32_t sK0 = sQ + 16384;
        uint32_t sV0 = sK0 + 8192;
        #pragma unroll
        for (int i = 0; i < 2; i++) {
            int idx = tid + i * 256;        // 0..511
            int r = idx >> 3, c8 = idx & 7;
            int sz = (r < Lk) ? 16 : 0;
            uint32_t so = (uint32_t)(r * 128 + ((c8 ^ (r & 7)) << 4));
            cp_async16(sK0 + so, Kbase + (size_t)r * kStride + c8 * 8, sz);
            cp_async16(sV0 + so, Vbase + (size_t)r * kStride + c8 * 8, sz);
        }
    }
    CP_COMMIT();

    int lrA = (lane & 7) | (lane & 8);
    int lkA8 = (lane >> 4) << 3;
    int lrB = (lane & 7) | ((lane & 16) >> 1);
    int lkB8 = lane & 8;
    int mV = lane >> 3;

    uint32_t qf[4][4];
    float oacc[8][4];
    #pragma unroll
    for (int fn = 0; fn < 8; fn++)
        #pragma unroll
        for (int e = 0; e < 4; e++) oacc[fn][e] = 0.f;
    float mrow[2] = { -1e30f, -1e30f };
    float lrow[2] = { 0.f, 0.f };

    for (int kt = 0; kt < nkt; kt++) {
        CP_WAIT(0);
        __syncthreads();
        int st = kt & 1;
        uint32_t sK = sQ + 16384 + (uint32_t)(st * 16384);
        uint32_t sV = sK + 8192;

        // prefetch next K/V into the other stage
        if (kt + 1 < nkt) {
            uint32_t sK1 = sQ + 16384 + (uint32_t)((1 - st) * 16384);
            uint32_t sV1 = sK1 + 8192;
            #pragma unroll
            for (int i = 0; i < 2; i++) {
                int idx = tid + i * 256;
                int r = idx >> 3, c8 = idx & 7;
                int jg = (kt + 1) * 64 + r;
                int sz = (jg < Lk) ? 16 : 0;
                uint32_t so = (uint32_t)(r * 128 + ((c8 ^ (r & 7)) << 4));
                cp_async16(sK1 + so, Kbase + (size_t)jg * kStride + c8 * 8, sz);
                cp_async16(sV1 + so, Vbase + (size_t)jg * kStride + c8 * 8, sz);
            }
        }
        CP_COMMIT();

        if (kt == 0) {
            #pragma unroll
            for (int kg = 0; kg < 4; kg++) {
                int r = wr + lrA;
                int c = kg * 16 + lkA8;
                uint32_t addr = sQ + (uint32_t)(r * 128 + (((c >> 3) ^ (r & 7)) << 4));
                LDMATRIX_X4(qf[kg][0], qf[kg][1], qf[kg][2], qf[kg][3], addr);
            }
        }

        // ---- S = Q @ K^T ----
        float sacc[8][4];
        #pragma unroll
        for (int fn = 0; fn < 8; fn++)
            #pragma unroll
            for (int e = 0; e < 4; e++) sacc[fn][e] = 0.f;
        #pragma unroll
        for (int kg = 0; kg < 4; kg++) {
            #pragma unroll
            for (int pp = 0; pp < 4; pp++) {
                int r = pp * 16 + lrB;
                int c = kg * 16 + lkB8;
                uint32_t addr = sK + (uint32_t)(r * 128 + (((c >> 3) ^ (r & 7)) << 4));
                uint32_t kb0, kb1, kb2, kb3;
                LDMATRIX_X4(kb0, kb1, kb2, kb3, addr);
                mma_f16(sacc[2 * pp][0], sacc[2 * pp][1], sacc[2 * pp][2], sacc[2 * pp][3],
                        qf[kg][0], qf[kg][1], qf[kg][2], qf[kg][3], kb0, kb1);
                mma_f16(sacc[2 * pp + 1][0], sacc[2 * pp + 1][1],
                        sacc[2 * pp + 1][2], sacc[2 * pp + 1][3],
                        qf[kg][0], qf[kg][1], qf[kg][2], qf[kg][3], kb2, kb3);
            }
        }
        #pragma unroll
        for (int fn = 0; fn < 8; fn++)
            #pragma unroll
            for (int e = 0; e < 4; e++) sacc[fn][e] *= scale;

        if (kt * 64 + 64 > Lk) {
            #pragma unroll
            for (int fn = 0; fn < 8; fn++) {
                int key0 = kt * 64 + fn * 8 + 2 * lc;
                if (key0 >= Lk)     { sacc[fn][0] = -1e30f; sacc[fn][2] = -1e30f; }
                if (key0 + 1 >= Lk) { sacc[fn][1] = -1e30f; sacc[fn][3] = -1e30f; }
            }
        }

        // ---- online softmax ----
        #pragma unroll
        for (int hr = 0; hr < 2; hr++) {
            float rm = -1e30f;
            #pragma unroll
            for (int fn = 0; fn < 8; fn++)
                rm = fmaxf(rm, fmaxf(sacc[fn][hr * 2], sacc[fn][hr * 2 + 1]));
            rm = fmaxf(rm, __shfl_xor_sync(0xffffffffu, rm, 1));
            rm = fmaxf(rm, __shfl_xor_sync(0xffffffffu, rm, 2));
            float mn = fmaxf(mrow[hr], rm);
            float rsum = 0.f;
            #pragma unroll
            for (int fn = 0; fn < 8; fn++) {
                float p0 = __expf(sacc[fn][hr * 2]     - mn);
                float p1 = __expf(sacc[fn][hr * 2 + 1] - mn);
                sacc[fn][hr * 2] = p0; sacc[fn][hr * 2 + 1] = p1;
                rsum += p0 + p1;
            }
            rsum += __shfl_xor_sync(0xffffffffu, rsum, 1);
            rsum += __shfl_xor_sync(0xffffffffu, rsum, 2);
            float alpha = __expf(mrow[hr] - mn);
            lrow[hr] = lrow[hr] * alpha + rsum;
            mrow[hr] = mn;
            #pragma unroll
            for (int fn = 0; fn < 8; fn++) {
                oacc[fn][hr * 2]     *= alpha;
                oacc[fn][hr * 2 + 1] *= alpha;
            }
        }

        // ---- P fragments (register repack) ----
        uint32_t pf[4][4];
        #pragma unroll
        for (int kg = 0; kg < 4; kg++) {
            pf[kg][0] = pack_h2(sacc[2 * kg][0],     sacc[2 * kg][1]);
            pf[kg][1] = pack_h2(sacc[2 * kg][2],     sacc[2 * kg][3]);
            pf[kg][2] = pack_h2(sacc[2 * kg + 1][0], sacc[2 * kg + 1][1]);
            pf[kg][3] = pack_h2(sacc[2 * kg + 1][2], sacc[2 * kg + 1][3]);
        }

        // ---- O += P @ V ----
        #pragma unroll
        for (int kg = 0; kg < 4; kg++) {
            #pragma unroll
            for (int dn = 0; dn < 4; dn++) {
                int r = kg * 16 + (mV & 1) * 8 + (lane & 7);
                int c8 = dn * 2 + (mV >> 1);
                uint32_t addr = sV + (uint32_t)(r * 128 + ((c8 ^ (r & 7)) << 4));
                uint32_t vb0, vb1, vb2, vb3;
                LDMATRIX_X4_T(vb0, vb1, vb2, vb3, addr);
                mma_f16(oacc[2 * dn][0], oacc[2 * dn][1],
                        oacc[2 * dn][2], oacc[2 * dn][3],
                        pf[kg][0], pf[kg][1], pf[kg][2], pf[kg][3], vb0, vb1);
                mma_f16(oacc[2 * dn + 1][0], oacc[2 * dn + 1][1],
                        oacc[2 * dn + 1][2], oacc[2 * dn + 1][3],
                        pf[kg][0], pf[kg][1], pf[kg][2], pf[kg][3], vb2, vb3);
            }
        }
        __syncthreads();
    }

    __half* Obase = O + (size_t)(b * Lq + qt * 128) * Dx + h * 64;
    #pragma unroll
    for (int hr = 0; hr < 2; hr++) {
        float inv = 1.f / lrow[hr];
        int row = wr + gr + hr * 8;
        #pragma unroll
        for (int fn = 0; fn < 8; fn++) {
            *(__half2*)(Obase + (size_t)row * Dx + fn * 8 + 2 * lc) =
                __floats2half2_rn(oacc[fn][hr * 2] * inv, oacc[fn][hr * 2 + 1] * inv);
        }
    }
}

// ----------------------------------------------------------------------------
// launch
// ----------------------------------------------------------------------------
template <typename T>
static inline T* sym(const void* s) {
    void* p = nullptr;
    cudaGetSymbolAddress(&p, s);
    return (T*)p;
}

static inline void hgemm(const __half* A, const __half* BT, const float* bias,
                         const float* res, float* Cf, __half* Ch,
                         int M, int N, int K, int act) {
    int ctas128 = (N / 128) * ((M + 127) / 128);
    if (ctas128 >= 148) {
        dim3 grid(N / 128, (M + 127) / 128);
        h_mma_gemm<128><<<grid, 256, GEMM_SMEM_128>>>(A, BT, bias, res, Cf, Ch, M, N, K, act);
    } else {
        dim3 grid(N / 128, (M + 63) / 64);
        h_mma_gemm<64><<<grid, 256, GEMM_SMEM_64>>>(A, BT, bias, res, Cf, Ch, M, N, K, act);
    }
}

extern "C" void kernel_launch(void* const* d_in, const int* in_sizes, int n_in,
                              void* d_out, int out_size) {
    const float* x     = (const float*)d_in[0];
    const float* c     = (const float*)d_in[1];
    const float* text  = (const float*)d_in[2];
    const float* W_ada = (const float*)d_in[3];
    const float* b_ada = (const float*)d_in[4];
    const float* W_qkv = (const float*)d_in[5];
    const float* b_qkv = (const float*)d_in[6];
    const float* W_proj= (const float*)d_in[7];
    const float* b_proj= (const float*)d_in[8];
    const float* W_ctx = (const float*)d_in[9];
    const float* b_ctx = (const float*)d_in[10];
    const float* W_q   = (const float*)d_in[11];
    const float* W_k   = (const float*)d_in[12];
    const float* W_v   = (const float*)d_in[13];
    const float* W_out = (const float*)d_in[14];
    const float* b_out = (const float*)d_in[15];
    const float* W_fc1 = (const float*)d_in[16];
    const float* b_fc1 = (const float*)d_in[17];
    const float* W_fc2 = (const float*)d_in[18];
    const float* b_fc2 = (const float*)d_in[19];
    float* out = (float*)d_out;

    float*  mod   = sym<float>(g_mod);
    float*  x1    = sym<float>(g_x1);
    float*  x2    = sym<float>(g_x2);
    __half* h     = sym<__half>(g_h);
    __half* qkvh  = sym<__half>(g_qkv);
    __half* attnh = sym<__half>(g_attn_h);
    __half* q2h   = sym<__half>(g_q2);
    __half* k2v2h = sym<__half>(g_k2v2);
    __half* ctxh  = sym<__half>(g_ctx_h);
    __half* texth = sym<__half>(g_text_h);
    __half* hidh  = sym<__half>(g_hid_h);

    __half* Wqkv_t = sym<__half>(g_Wqkv_t);
    __half* Wproj_t= sym<__half>(g_Wproj_t);
    __half* Wctx_t = sym<__half>(g_Wctx_t);
    __half* Wq_t   = sym<__half>(g_Wq_t);
    __half* Wkv_t  = sym<__half>(g_Wkv_t);
    __half* Wout_t = sym<__half>(g_Wout_t);
    __half* Wfc1_t = sym<__half>(g_Wfc1_t);
    __half* Wfc2_t = sym<__half>(g_Wfc2_t);

    cudaFuncSetAttribute(attn_h_kernel, cudaFuncAttributeMaxDynamicSharedMemorySize,
                         ATTN_SMEM);
    cudaFuncSetAttribute(h_mma_gemm<128>, cudaFuncAttributeMaxDynamicSharedMemorySize,
                         GEMM_SMEM_128);
    cudaFuncSetAttribute(h_mma_gemm<64>, cudaFuncAttributeMaxDynamicSharedMemorySize,
                         GEMM_SMEM_64);

    // ---- batched weight transpose (one launch) ----
    TransJobs tj;
    const float* tin[NTJOBS] = { W_qkv, W_proj, W_fc1, W_ctx, W_q, W_k, W_v, W_out, W_fc2 };
    __half* tout[NTJOBS] = { Wqkv_t, Wproj_t, Wfc1_t, Wctx_t, Wq_t, Wkv_t,
                             Wkv_t + Dx * Dx, Wout_t, Wfc2_t };
    int tK[NTJOBS] = { Dx, Dx, Dx, TDx, Dx, Dx, Dx, Dx, 4 * Dx };
    int tN[NTJOBS] = { 3 * Dx, Dx, 4 * Dx, Dx, Dx, Dx, Dx, Dx, Dx };
    int total = 0;
    for (int j = 0; j < NTJOBS; j++) {
        tj.in[j] = tin[j]; tj.out[j] = tout[j];
        tj.K[j] = tK[j]; tj.N[j] = tN[j];
        tj.base[j] = total;
        total += (tN[j] >> 5) * (tK[j] >> 5);
    }

    dim3 tb(32, 8);
    transpose_batch_kernel<<<total, tb>>>(tj);                                   // 0
    ada_mod_kernel<<<dim3(24, 4), 256>>>(c, W_ada, b_ada, mod);                  // 1
    ln_mod_kernel<<<ROWS, 256>>>(x, mod, h, 0);                                  // 2
    f2h_kernel<<<(CTXROWS * TDx + 255) / 256, 256>>>(text, texth, CTXROWS * TDx);// 3
    hgemm(h, Wqkv_t, b_qkv, nullptr, nullptr, qkvh, ROWS, 3 * Dx, Dx, ACT_NONE); // 4
    attn_h_kernel<<<dim3(Nx / 128, Hx, Bx), 256, ATTN_SMEM>>>(                   // 5 (ncu)
        qkvh, 3 * Dx, qkvh + Dx, qkvh + 2 * Dx, 3 * Dx, attnh, Nx, Nx);
    hgemm(attnh, Wproj_t, b_proj, x, x1, nullptr, ROWS, Dx, Dx, ACT_NONE);

    // --- cross attention ---
    ln_mod_kernel<<<ROWS, 256>>>(x1, mod, h, 2);
    hgemm(texth, Wctx_t, b_ctx, nullptr, nullptr, ctxh, CTXROWS, Dx, TDx, ACT_NONE);
    hgemm(h, Wq_t, nullptr, nullptr, nullptr, q2h, ROWS, Dx, Dx, ACT_NONE);
    hgemm(ctxh, Wkv_t, nullptr, nullptr, nullptr, k2v2h, CTXROWS, 2 * Dx, Dx, ACT_NONE);
    attn_h_kernel<<<dim3(Nx / 128, Hx, Bx), 256, ATTN_SMEM>>>(
        q2h, Dx, k2v2h, k2v2h + Dx, 2 * Dx, attnh, Nx, TLx);
    hgemm(attnh, Wout_t, b_out, x1, x2, nullptr, ROWS, Dx, Dx, ACT_NONE);

    // --- MLP ---
    ln_mod_kernel<<<ROWS, 256>>>(x2, mod, h, 4);
    hgemm(h, Wfc1_t, b_fc1, nullptr, nullptr, hidh, ROWS, 4 * Dx, Dx, ACT_GELU);
    hgemm(hidh, Wfc2_t, b_fc2, x2, out, nullptr, ROWS, Dx, 4 * Dx, ACT_NONE);
}

// round 13
// speedup vs baseline: 1.0247x; 1.0247x over previous
#include <cuda_runtime.h>
#include <cuda_fp16.h>
#include <cstdint>
#include <math.h>

// ----------------------------------------------------------------------------
// DiT block: adaLN -> self-attn -> cross-attn -> MLP (GELU tanh)
// Round 13: revert to 64-row attention (R11); GEMM issues next-stage cp.async
//           BEFORE the MMA block (extra latency slack).
// ----------------------------------------------------------------------------

#define Bx 4
#define Nx 1024
#define Dx 1024
#define Hx 16
#define HDx 64
#define TDx 768
#define TLx 77
#define ROWS (Bx * Nx)       // 4096
#define CTXROWS (Bx * TLx)   // 308

// fp32 scratch
__device__ float g_mod[Bx * 6 * Dx];
__device__ float g_x1[ROWS * Dx];
__device__ float g_x2[ROWS * Dx];
// half scratch
__device__ __half g_h[ROWS * Dx];
__device__ __half g_qkv[ROWS * 3 * Dx];
__device__ __half g_attn_h[ROWS * Dx];
__device__ __half g_q2[ROWS * Dx];
__device__ __half g_k2v2[CTXROWS * 2 * Dx];
__device__ __half g_ctx_h[CTXROWS * Dx];
__device__ __half g_text_h[CTXROWS * TDx];
__device__ __half g_hid_h[ROWS * 4 * Dx];
// transposed (K-major [N,K]) fp16 weights
__device__ __half g_Wqkv_t[3 * Dx * Dx];
__device__ __half g_Wproj_t[Dx * Dx];
__device__ __half g_Wctx_t[Dx * TDx];
__device__ __half g_Wq_t[Dx * Dx];
__device__ __half g_Wkv_t[2 * Dx * Dx];
__device__ __half g_Wout_t[Dx * Dx];
__device__ __half g_Wfc1_t[4 * Dx * Dx];
__device__ __half g_Wfc2_t[4 * Dx * Dx];

// ----------------------------------------------------------------------------
// helpers
// ----------------------------------------------------------------------------
__device__ __forceinline__ uint32_t smem_u32(const void* p) {
    uint32_t a;
    asm("{ .reg .u64 t; cvta.to.shared.u64 t, %1; cvt.u32.u64 %0, t; }"
        : "=r"(a) : "l"(p));
    return a;
}
__device__ __forceinline__ void cp_async16(uint32_t saddr, const void* gaddr, int szbytes) {
    asm volatile("cp.async.cg.shared.global [%0], [%1], 16, %2;"
                 :: "r"(saddr), "l"(gaddr), "r"(szbytes) : "memory");
}
#define CP_COMMIT() asm volatile("cp.async.commit_group;" ::: "memory")
#define CP_WAIT(n)  asm volatile("cp.async.wait_group %0;" :: "n"(n) : "memory")

#define LDMATRIX_X4(r0, r1, r2, r3, addr) \
    asm volatile("ldmatrix.sync.aligned.m8n8.x4.shared.b16 {%0,%1,%2,%3}, [%4];" \
                 : "=r"(r0), "=r"(r1), "=r"(r2), "=r"(r3) : "r"(addr))
#define LDMATRIX_X4_T(r0, r1, r2, r3, addr) \
    asm volatile("ldmatrix.sync.aligned.m8n8.x4.trans.shared.b16 {%0,%1,%2,%3}, [%4];" \
                 : "=r"(r0), "=r"(r1), "=r"(r2), "=r"(r3) : "r"(addr))

__device__ __forceinline__ void mma_f16(float& c0, float& c1, float& c2, float& c3,
                                        uint32_t a0, uint32_t a1, uint32_t a2, uint32_t a3,
                                        uint32_t b0, uint32_t b1) {
    asm volatile(
        "mma.sync.aligned.m16n8k16.row.col.f32.f16.f16.f32 "
        "{%0,%1,%2,%3}, {%4,%5,%6,%7}, {%8,%9}, {%0,%1,%2,%3};"
        : "+f"(c0), "+f"(c1), "+f"(c2), "+f"(c3)
        : "r"(a0), "r"(a1), "r"(a2), "r"(a3), "r"(b0), "r"(b1));
}
__device__ __forceinline__ uint32_t pack_h2(float lo, float hi) {
    __half2 h = __floats2half2_rn(lo, hi);
    return *(uint32_t*)&h;
}

// ----------------------------------------------------------------------------
// batched weight transpose
// ----------------------------------------------------------------------------
#define NTJOBS 9
struct TransJobs {
    const float* in[NTJOBS];
    __half* out[NTJOBS];
    int K[NTJOBS];
    int N[NTJOBS];
    int base[NTJOBS];
};

__global__ void transpose_batch_kernel(TransJobs jobs) {
    __shared__ float t[32][33];
    int bid = blockIdx.x;
    int j = 0;
    #pragma unroll
    for (int i = 1; i < NTJOBS; i++)
        if (bid >= jobs.base[i]) j = i;
    int tloc = bid - jobs.base[j];
    int K = jobs.K[j], N = jobs.N[j];
    int tiles_x = N >> 5;
    int n0 = (tloc % tiles_x) << 5;
    int k0 = (tloc / tiles_x) << 5;
    const float* in = jobs.in[j];
    __half* out = jobs.out[j];
    int tx = threadIdx.x, ty = threadIdx.y;
    #pragma unroll
    for (int i = 0; i < 32; i += 8)
        t[ty + i][tx] = in[(size_t)(k0 + ty + i) * N + n0 + tx];
    __syncthreads();
    #pragma unroll
    for (int i = 0; i < 32; i += 8)
        out[(size_t)(n0 + ty + i) * K + k0 + tx] = __float2half(t[tx][ty + i]);
}

__global__ void f2h_kernel(const float* __restrict__ in, __half* __restrict__ out, int n) {
    int i = blockIdx.x * 256 + threadIdx.x;
    if (i < n) out[i] = __float2half(in[i]);
}

// ----------------------------------------------------------------------------
// adaLN modulation
// ----------------------------------------------------------------------------
__global__ void ada_mod_kernel(const float* __restrict__ c,
                               const float* __restrict__ Wada,
                               const float* __restrict__ bada,
                               float* __restrict__ mod) {
    __shared__ float sc[Dx];
    int b = blockIdx.y;
    for (int i = threadIdx.x; i < Dx; i += 256) {
        float v = c[b * Dx + i];
        sc[i] = v / (1.f + __expf(-v));
    }
    __syncthreads();
    int n = blockIdx.x * 256 + threadIdx.x;
    float acc = 0.f;
    for (int k = 0; k < Dx; k++)
        acc += sc[k] * Wada[(size_t)k * (6 * Dx) + n];
    mod[b * 6 * Dx + n] = acc + bada[n];
}

// ----------------------------------------------------------------------------
// LayerNorm + modulate -> fp16
// ----------------------------------------------------------------------------
__global__ void ln_mod_kernel(const float* __restrict__ x,
                              const float* __restrict__ mod,
                              __half* __restrict__ out, int chunk) {
    int row = blockIdx.x;
    int b = row >> 10;
    int tid = threadIdx.x;
    const float* xr = x + (size_t)row * Dx;
    float4 v = *(const float4*)(xr + tid * 4);
    float s = v.x + v.y + v.z + v.w;
    float ss = v.x * v.x + v.y * v.y + v.z * v.z + v.w * v.w;
    #pragma unroll
    for (int off = 16; off; off >>= 1) {
        s  += __shfl_xor_sync(0xffffffffu, s, off);
        ss += __shfl_xor_sync(0xffffffffu, ss, off);
    }
    __shared__ float rs[8], rss[8];
    int wid = tid >> 5, lane = tid & 31;
    if (!lane) { rs[wid] = s; rss[wid] = ss; }
    __syncthreads();
    s = 0.f; ss = 0.f;
    #pragma unroll
    for (int w = 0; w < 8; w++) { s += rs[w]; ss += rss[w]; }
    float mean = s * (1.f / Dx);
    float var = ss * (1.f / Dx) - mean * mean;
    float inv = rsqrtf(var + 1e-6f);
    const float* sh = mod + (size_t)b * 6 * Dx + (size_t)chunk * Dx;
    const float* scl = sh + Dx;
    int d = tid * 4;
    float o0 = (v.x - mean) * inv * (1.f + scl[d + 0]) + sh[d + 0];
    float o1 = (v.y - mean) * inv * (1.f + scl[d + 1]) + sh[d + 1];
    float o2 = (v.z - mean) * inv * (1.f + scl[d + 2]) + sh[d + 2];
    float o3 = (v.w - mean) * inv * (1.f + scl[d + 3]) + sh[d + 3];
    __half2* op = (__half2*)(out + (size_t)row * Dx + d);
    op[0] = __floats2half2_rn(o0, o1);
    op[1] = __floats2half2_rn(o2, o3);
}

// ----------------------------------------------------------------------------
// fp16 mma.sync GEMM, cp.async 3-stage, templated M-tile (BM = 128 or 64).
// Next-stage cp.async issued BEFORE the MMA block (buffer (s+2)%3 was freed
// by the iteration-top __syncthreads; loads get a full MMA block of slack).
// ----------------------------------------------------------------------------
#define ACT_NONE 0
#define ACT_GELU 1
#define STAGES 3

__device__ __forceinline__ float gelu_tanh(float x) {
    float x3 = x * x * x;
    return 0.5f * x * (1.f + tanhf(0.7978845608028654f * (x + 0.044715f * x3)));
}

template <int BM>
__global__ __launch_bounds__(256, 2)
void h_mma_gemm(const __half* __restrict__ A, const __half* __restrict__ BT,
                const float* __restrict__ bias, const float* __restrict__ res,
                float* __restrict__ Cf, __half* __restrict__ Ch,
                int M, int N, int K, int act) {
    constexpr int STAGE_BYTES = (BM + 128) * 128;
    constexpr int ACH = BM / 32;
    constexpr int IM = BM / 32;
    extern __shared__ char smem[];
    uint32_t sbase = smem_u32(smem);
    int tid = threadIdx.x, lane = tid & 31, wid = tid >> 5;
    int wm = wid >> 2, wn = wid & 3;
    int row0 = blockIdx.y * BM, col0 = blockIdx.x * 128;

    uint32_t offA[4], offB[4];
    const __half* gA[4];
    const __half* gB[4];
    int szA[4];
    #pragma unroll
    for (int i = 0; i < ACH; i++) {
        int idx = tid + i * 256;
        int r = idx >> 3, c8 = idx & 7;
        offA[i] = (uint32_t)(r * 128 + ((c8 ^ (r & 7)) << 4));
        szA[i] = (row0 + r) < M ? 16 : 0;
        gA[i] = A + (size_t)(row0 + r) * K + c8 * 8;
    }
    #pragma unroll
    for (int i = 0; i < 4; i++) {
        int idx = tid + i * 256;
        int r = idx >> 3, c8 = idx & 7;
        offB[i] = (uint32_t)(BM * 128 + r * 128 + ((c8 ^ (r & 7)) << 4));
        gB[i] = BT + (size_t)(col0 + r) * K + c8 * 8;
    }

    float acc[IM][4][4];
    #pragma unroll
    for (int im = 0; im < IM; im++)
        #pragma unroll
        for (int jn = 0; jn < 4; jn++)
            #pragma unroll
            for (int e = 0; e < 4; e++) acc[im][jn][e] = 0.f;

    int K64 = K >> 6;

    #pragma unroll
    for (int s = 0; s < STAGES - 1; s++) {
        uint32_t sa = sbase + (uint32_t)(s * STAGE_BYTES);
        #pragma unroll
        for (int i = 0; i < ACH; i++)
            cp_async16(sa + offA[i], gA[i] + (size_t)s * 64, szA[i]);
        #pragma unroll
        for (int i = 0; i < 4; i++)
            cp_async16(sa + offB[i], gB[i] + (size_t)s * 64, 16);
        CP_COMMIT();
    }

    int lrA = (lane & 7) | (lane & 8);
    int lkA8 = (lane >> 4) << 3;
    int lrB = (lane & 7) | ((lane & 16) >> 1);
    int lkB8 = lane & 8;

    for (int s = 0; s < K64; s++) {
        CP_WAIT(STAGES - 2);
        __syncthreads();

        // issue next stage FIRST (into buffer freed by the sync above)
        int sn = s + STAGES - 1;
        if (sn < K64) {
            uint32_t sa2 = sbase + (uint32_t)((sn % STAGES) * STAGE_BYTES);
            #pragma unroll
            for (int i = 0; i < ACH; i++)
                cp_async16(sa2 + offA[i], gA[i] + (size_t)sn * 64, szA[i]);
            #pragma unroll
            for (int i = 0; i < 4; i++)
                cp_async16(sa2 + offB[i], gB[i] + (size_t)sn * 64, 16);
        }
        CP_COMMIT();

        uint32_t sa = sbase + (uint32_t)((s % STAGES) * STAGE_BYTES);
        uint32_t sb = sa + (uint32_t)(BM * 128);

        #pragma unroll
        for (int kg = 0; kg < 4; kg++) {
            int lkA = kg * 16 + lkA8;
            int lkB = kg * 16 + lkB8;
            uint32_t areg[IM][4];
            #pragma unroll
            for (int im = 0; im < IM; im++) {
                int r = wm * (BM / 2) + im * 16 + lrA;
                uint32_t addr = sa + (uint32_t)(r * 128 + (((lkA >> 3) ^ (r & 7)) << 4));
                LDMATRIX_X4(areg[im][0], areg[im][1], areg[im][2], areg[im][3], addr);
            }
            uint32_t breg[2][4];
            #pragma unroll
            for (int p = 0; p < 2; p++) {
                int r = wn * 32 + p * 16 + lrB;
                uint32_t addr = sb + (uint32_t)(r * 128 + (((lkB >> 3) ^ (r & 7)) << 4));
                LDMATRIX_X4(breg[p][0], breg[p][1], breg[p][2], breg[p][3], addr);
            }
            #pragma unroll
            for (int im = 0; im < IM; im++)
                #pragma unroll
                for (int jn = 0; jn < 4; jn++) {
                    int p = jn >> 1, q = (jn & 1) * 2;
                    mma_f16(acc[im][jn][0], acc[im][jn][1],
                            acc[im][jn][2], acc[im][jn][3],
                            areg[im][0], areg[im][1], areg[im][2], areg[im][3],
                            breg[p][q], breg[p][q + 1]);
                }
        }
    }

    int egr = lane >> 2, egc = (lane & 3) * 2;
    #pragma unroll
    for (int im = 0; im < IM; im++) {
        #pragma unroll
        for (int half = 0; half < 2; half++) {
            int rg = row0 + wm * (BM / 2) + im * 16 + egr + half * 8;
            if (rg >= M) continue;
            #pragma unroll
            for (int jn = 0; jn < 4; jn++) {
                int cg = col0 + wn * 32 + jn * 8 + egc;
                float t0 = acc[im][jn][half * 2 + 0];
                float t1 = acc[im][jn][half * 2 + 1];
                if (bias) { t0 += bias[cg]; t1 += bias[cg + 1]; }
                if (act == ACT_GELU) { t0 = gelu_tanh(t0); t1 = gelu_tanh(t1); }
                if (res) {
                    t0 += res[(size_t)rg * N + cg];
                    t1 += res[(size_t)rg * N + cg + 1];
                }
                if (Ch) {
                    *(__half2*)(Ch + (size_t)rg * N + cg) = __floats2half2_rn(t0, t1);
                } else {
                    *(float2*)(Cf + (size_t)rg * N + cg) = make_float2(t0, t1);
                }
            }
        }
    }
}

#define GEMM_SMEM_128 (STAGES * (128 + 128) * 128)
#define GEMM_SMEM_64  (STAGES * (64 + 128) * 128)

// ----------------------------------------------------------------------------
// fp16 ldmatrix/mma flash attention, 64 q-rows, double-buffered K/V
// (reverted to round-11 proven version)
// ----------------------------------------------------------------------------
#define ATTN_SMEM (8192 + 2 * 16384)

__global__ __launch_bounds__(128, 3)
void attn_h_kernel(const __half* __restrict__ Q, int qStride,
                   const __half* __restrict__ K, const __half* __restrict__ V,
                   int kStride, __half* __restrict__ O, int Lq, int Lk) {
    extern __shared__ char smc[];
    uint32_t sQ = smem_u32(smc);

    int tid = threadIdx.x, lane = tid & 31, w = tid >> 5;
    int gr = lane >> 2, lc = lane & 3;
    int qt = blockIdx.x, h = blockIdx.y, b = blockIdx.z;
    int wr = w * 16;
    const float scale = 0.125f;

    const __half* Kbase = K + (size_t)(b * Lk) * kStride + h * 64;
    const __half* Vbase = V + (size_t)(b * Lk) * kStride + h * 64;
    int nkt = (Lk + 63) >> 6;

    const __half* Qbase = Q + (size_t)(b * Lq + qt * 64) * qStride + h * 64;
    #pragma unroll
    for (int i = 0; i < 4; i++) {
        int idx = tid + i * 128;
        int r = idx >> 3, c8 = idx & 7;
        cp_async16(sQ + r * 128 + ((c8 ^ (r & 7)) << 4),
                   Qbase + (size_t)r * qStride + c8 * 8, 16);
    }
    {
        uint32_t sK0 = sQ + 8192;
        uint32_t sV0 = sK0 + 8192;
        #pragma unroll
        for (int i = 0; i < 4; i++) {
            int idx = tid + i * 128;
            int r = idx >> 3, c8 = idx & 7;
            int sz = (r < Lk) ? 16 : 0;
            uint32_t so = (uint32_t)(r * 128 + ((c8 ^ (r & 7)) << 4));
            cp_async16(sK0 + so, Kbase + (size_t)r * kStride + c8 * 8, sz);
            cp_async16(sV0 + so, Vbase + (size_t)r * kStride + c8 * 8, sz);
        }
    }
    CP_COMMIT();

    int lrA = (lane & 7) | (lane & 8);
    int lkA8 = (lane >> 4) << 3;
    int lrB = (lane & 7) | ((lane & 16) >> 1);
    int lkB8 = lane & 8;
    int mV = lane >> 3;

    uint32_t qf[4][4];
    float oacc[8][4];
    #pragma unroll
    for (int fn = 0; fn < 8; fn++)
        #pragma unroll
        for (int e = 0; e < 4; e++) oacc[fn][e] = 0.f;
    float mrow[2] = { -1e30f, -1e30f };
    float lrow[2] = { 0.f, 0.f };

    for (int kt = 0; kt < nkt; kt++) {
        CP_WAIT(0);
        __syncthreads();
        int st = kt & 1;
        uint32_t sK = sQ + 8192 + (uint32_t)(st * 16384);
        uint32_t sV = sK + 8192;

        if (kt + 1 < nkt) {
            uint32_t sK1 = sQ + 8192 + (uint32_t)((1 - st) * 16384);
            uint32_t sV1 = sK1 + 8192;
            #pragma unroll
            for (int i = 0; i < 4; i++) {
                int idx = tid + i * 128;
                int r = idx >> 3, c8 = idx & 7;
                int jg = (kt + 1) * 64 + r;
                int sz = (jg < Lk) ? 16 : 0;
                uint32_t so = (uint32_t)(r * 128 + ((c8 ^ (r & 7)) << 4));
                cp_async16(sK1 + so, Kbase + (size_t)jg * kStride + c8 * 8, sz);
                cp_async16(sV1 + so, Vbase + (size_t)jg * kStride + c8 * 8, sz);
            }
        }
        CP_COMMIT();

        if (kt == 0) {
            #pragma unroll
            for (int kg = 0; kg < 4; kg++) {
                int r = wr + lrA;
                int c = kg * 16 + lkA8;
                uint32_t addr = sQ + (uint32_t)(r * 128 + (((c >> 3) ^ (r & 7)) << 4));
                LDMATRIX_X4(qf[kg][0], qf[kg][1], qf[kg][2], qf[kg][3], addr);
            }
        }

        float sacc[8][4];
        #pragma unroll
        for (int fn = 0; fn < 8; fn++)
            #pragma unroll
            for (int e = 0; e < 4; e++) sacc[fn][e] = 0.f;
        #pragma unroll
        for (int kg = 0; kg < 4; kg++) {
            #pragma unroll
            for (int pp = 0; pp < 4; pp++) {
                int r = pp * 16 + lrB;
                int c = kg * 16 + lkB8;
                uint32_t addr = sK + (uint32_t)(r * 128 + (((c >> 3) ^ (r & 7)) << 4));
                uint32_t kb0, kb1, kb2, kb3;
                LDMATRIX_X4(kb0, kb1, kb2, kb3, addr);
                mma_f16(sacc[2 * pp][0], sacc[2 * pp][1], sacc[2 * pp][2], sacc[2 * pp][3],
                        qf[kg][0], qf[kg][1], qf[kg][2], qf[kg][3], kb0, kb1);
                mma_f16(sacc[2 * pp + 1][0], sacc[2 * pp + 1][1],
                        sacc[2 * pp + 1][2], sacc[2 * pp + 1][3],
                        qf[kg][0], qf[kg][1], qf[kg][2], qf[kg][3], kb2, kb3);
            }
        }
        #pragma unroll
        for (int fn = 0; fn < 8; fn++)
            #pragma unroll
            for (int e = 0; e < 4; e++) sacc[fn][e] *= scale;

        if (kt * 64 + 64 > Lk) {
            #pragma unroll
            for (int fn = 0; fn < 8; fn++) {
                int key0 = kt * 64 + fn * 8 + 2 * lc;
                if (key0 >= Lk)     { sacc[fn][0] = -1e30f; sacc[fn][2] = -1e30f; }
                if (key0 + 1 >= Lk) { sacc[fn][1] = -1e30f; sacc[fn][3] = -1e30f; }
            }
        }

        #pragma unroll
        for (int hr = 0; hr < 2; hr++) {
            float rm = -1e30f;
            #pragma unroll
            for (int fn = 0; fn < 8; fn++)
                rm = fmaxf(rm, fmaxf(sacc[fn][hr * 2], sacc[fn][hr * 2 + 1]));
            rm = fmaxf(rm, __shfl_xor_sync(0xffffffffu, rm, 1));
            rm = fmaxf(rm, __shfl_xor_sync(0xffffffffu, rm, 2));
            float mn = fmaxf(mrow[hr], rm);
            float rsum = 0.f;
            #pragma unroll
            for (int fn = 0; fn < 8; fn++) {
                float p0 = __expf(sacc[fn][hr * 2]     - mn);
                float p1 = __expf(sacc[fn][hr * 2 + 1] - mn);
                sacc[fn][hr * 2] = p0; sacc[fn][hr * 2 + 1] = p1;
                rsum += p0 + p1;
            }
            rsum += __shfl_xor_sync(0xffffffffu, rsum, 1);
            rsum += __shfl_xor_sync(0xffffffffu, rsum, 2);
            float alpha = __expf(mrow[hr] - mn);
            lrow[hr] = lrow[hr] * alpha + rsum;
            mrow[hr] = mn;
            #pragma unroll
            for (int fn = 0; fn < 8; fn++) {
                oacc[fn][hr * 2]     *= alpha;
                oacc[fn][hr * 2 + 1] *= alpha;
            }
        }

        uint32_t pf[4][4];
        #pragma unroll
        for (int kg = 0; kg < 4; kg++) {
            pf[kg][0] = pack_h2(sacc[2 * kg][0],     sacc[2 * kg][1]);
            pf[kg][1] = pack_h2(sacc[2 * kg][2],     sacc[2 * kg][3]);
            pf[kg][2] = pack_h2(sacc[2 * kg + 1][0], sacc[2 * kg + 1][1]);
            pf[kg][3] = pack_h2(sacc[2 * kg + 1][2], sacc[2 * kg + 1][3]);
        }

        #pragma unroll
        for (int kg = 0; kg < 4; kg++) {
            #pragma unroll
            for (int dn = 0; dn < 4; dn++) {
                int r = kg * 16 + (mV & 1) * 8 + (lane & 7);
                int c8 = dn * 2 + (mV >> 1);
                uint32_t addr = sV + (uint32_t)(r * 128 + ((c8 ^ (r & 7)) << 4));
                uint32_t vb0, vb1, vb2, vb3;
                LDMATRIX_X4_T(vb0, vb1, vb2, vb3, addr);
                mma_f16(oacc[2 * dn][0], oacc[2 * dn][1],
                        oacc[2 * dn][2], oacc[2 * dn][3],
                        pf[kg][0], pf[kg][1], pf[kg][2], pf[kg][3], vb0, vb1);
                mma_f16(oacc[2 * dn + 1][0], oacc[2 * dn + 1][1],
                        oacc[2 * dn + 1][2], oacc[2 * dn + 1][3],
                        pf[kg][0], pf[kg][1], pf[kg][2], pf[kg][3], vb2, vb3);
            }
        }
        __syncthreads();
    }

    __half* Obase = O + (size_t)(b * Lq + qt * 64) * Dx + h * 64;
    #pragma unroll
    for (int hr = 0; hr < 2; hr++) {
        float inv = 1.f / lrow[hr];
        int row = wr + gr + hr * 8;
        #pragma unroll
        for (int fn = 0; fn < 8; fn++) {
            *(__half2*)(Obase + (size_t)row * Dx + fn * 8 + 2 * lc) =
                __floats2half2_rn(oacc[fn][hr * 2] * inv, oacc[fn][hr * 2 + 1] * inv);
        }
    }
}

// ----------------------------------------------------------------------------
// launch
// ----------------------------------------------------------------------------
template <typename T>
static inline T* sym(const void* s) {
    void* p = nullptr;
    cudaGetSymbolAddress(&p, s);
    return (T*)p;
}

static inline void hgemm(const __half* A, const __half* BT, const float* bias,
                         const float* res, float* Cf, __half* Ch,
                         int M, int N, int K, int act) {
    int ctas128 = (N / 128) * ((M + 127) / 128);
    if (ctas128 >= 148) {
        dim3 grid(N / 128, (M + 127) / 128);
        h_mma_gemm<128><<<grid, 256, GEMM_SMEM_128>>>(A, BT, bias, res, Cf, Ch, M, N, K, act);
    } else {
        dim3 grid(N / 128, (M + 63) / 64);
        h_mma_gemm<64><<<grid, 256, GEMM_SMEM_64>>>(A, BT, bias, res, Cf, Ch, M, N, K, act);
    }
}

extern "C" void kernel_launch(void* const* d_in, const int* in_sizes, int n_in,
                              void* d_out, int out_size) {
    const float* x     = (const float*)d_in[0];
    const float* c     = (const float*)d_in[1];
    const float* text  = (const float*)d_in[2];
    const float* W_ada = (const float*)d_in[3];
    const float* b_ada = (const float*)d_in[4];
    const float* W_qkv = (const float*)d_in[5];
    const float* b_qkv = (const float*)d_in[6];
    const float* W_proj= (const float*)d_in[7];
    const float* b_proj= (const float*)d_in[8];
    const float* W_ctx = (const float*)d_in[9];
    const float* b_ctx = (const float*)d_in[10];
    const float* W_q   = (const float*)d_in[11];
    const float* W_k   = (const float*)d_in[12];
    const float* W_v   = (const float*)d_in[13];
    const float* W_out = (const float*)d_in[14];
    const float* b_out = (const float*)d_in[15];
    const float* W_fc1 = (const float*)d_in[16];
    const float* b_fc1 = (const float*)d_in[17];
    const float* W_fc2 = (const float*)d_in[18];
    const float* b_fc2 = (const float*)d_in[19];
    float* out = (float*)d_out;

    float*  mod   = sym<float>(g_mod);
    float*  x1    = sym<float>(g_x1);
    float*  x2    = sym<float>(g_x2);
    __half* h     = sym<__half>(g_h);
    __half* qkvh  = sym<__half>(g_qkv);
    __half* attnh = sym<__half>(g_attn_h);
    __half* q2h   = sym<__half>(g_q2);
    __half* k2v2h = sym<__half>(g_k2v2);
    __half* ctxh  = sym<__half>(g_ctx_h);
    __half* texth = sym<__half>(g_text_h);
    __half* hidh  = sym<__half>(g_hid_h);

    __half* Wqkv_t = sym<__half>(g_Wqkv_t);
    __half* Wproj_t= sym<__half>(g_Wproj_t);
    __half* Wctx_t = sym<__half>(g_Wctx_t);
    __half* Wq_t   = sym<__half>(g_Wq_t);
    __half* Wkv_t  = sym<__half>(g_Wkv_t);
    __half* Wout_t = sym<__half>(g_Wout_t);
    __half* Wfc1_t = sym<__half>(g_Wfc1_t);
    __half* Wfc2_t = sym<__half>(g_Wfc2_t);

    cudaFuncSetAttribute(attn_h_kernel, cudaFuncAttributeMaxDynamicSharedMemorySize,
                         ATTN_SMEM);
    cudaFuncSetAttribute(h_mma_gemm<128>, cudaFuncAttributeMaxDynamicSharedMemorySize,
                         GEMM_SMEM_128);
    cudaFuncSetAttribute(h_mma_gemm<64>, cudaFuncAttributeMaxDynamicSharedMemorySize,
                         GEMM_SMEM_64);

    // ---- batched weight transpose (one launch) ----
    TransJobs tj;
    const float* tin[NTJOBS] = { W_qkv, W_proj, W_fc1, W_ctx, W_q, W_k, W_v, W_out, W_fc2 };
    __half* tout[NTJOBS] = { Wqkv_t, Wproj_t, Wfc1_t, Wctx_t, Wq_t, Wkv_t,
                             Wkv_t + Dx * Dx, Wout_t, Wfc2_t };
    int tK[NTJOBS] = { Dx, Dx, Dx, TDx, Dx, Dx, Dx, Dx, 4 * Dx };
    int tN[NTJOBS] = { 3 * Dx, Dx, 4 * Dx, Dx, Dx, Dx, Dx, Dx, Dx };
    int total = 0;
    for (int j = 0; j < NTJOBS; j++) {
        tj.in[j] = tin[j]; tj.out[j] = tout[j];
        tj.K[j] = tK[j]; tj.N[j] = tN[j];
        tj.base[j] = total;
        total += (tN[j] >> 5) * (tK[j] >> 5);
    }

    dim3 tb(32, 8);
    transpose_batch_kernel<<<total, tb>>>(tj);                                   // 0
    ada_mod_kernel<<<dim3(24, 4), 256>>>(c, W_ada, b_ada, mod);                  // 1
    ln_mod_kernel<<<ROWS, 256>>>(x, mod, h, 0);                                  // 2
    f2h_kernel<<<(CTXROWS * TDx + 255) / 256, 256>>>(text, texth, CTXROWS * TDx);// 3
    hgemm(h, Wqkv_t, b_qkv, nullptr, nullptr, qkvh, ROWS, 3 * Dx, Dx, ACT_NONE); // 4
    attn_h_kernel<<<dim3(Nx / 64, Hx, Bx), 128, ATTN_SMEM>>>(                    // 5 (ncu)
        qkvh, 3 * Dx, qkvh + Dx, qkvh + 2 * Dx, 3 * Dx, attnh, Nx, Nx);
    hgemm(attnh, Wproj_t, b_proj, x, x1, nullptr, ROWS, Dx, Dx, ACT_NONE);

    // --- cross attention ---
    ln_mod_kernel<<<ROWS, 256>>>(x1, mod, h, 2);
    hgemm(texth, Wctx_t, b_ctx, nullptr, nullptr, ctxh, CTXROWS, Dx, TDx, ACT_NONE);
    hgemm(h, Wq_t, nullptr, nullptr, nullptr, q2h, ROWS, Dx, Dx, ACT_NONE);
    hgemm(ctxh, Wkv_t, nullptr, nullptr, nullptr, k2v2h, CTXROWS, 2 * Dx, Dx, ACT_NONE);
    attn_h_kernel<<<dim3(Nx / 64, Hx, Bx), 128, ATTN_SMEM>>>(
        q2h, Dx, k2v2h, k2v2h + Dx, 2 * Dx, attnh, Nx, TLx);
    hgemm(attnh, Wout_t, b_out, x1, x2, nullptr, ROWS, Dx, Dx, ACT_NONE);

    // --- MLP ---
    ln_mod_kernel<<<ROWS, 256>>>(x2, mod, h, 4);
    hgemm(h, Wfc1_t, b_fc1, nullptr, nullptr, hidh, ROWS, 4 * Dx, Dx, ACT_GELU);
    hgemm(hidh, Wfc2_t, b_fc2, x2, out, nullptr, ROWS, Dx, 4 * Dx, ACT_NONE);
}